// round 16
// baseline (speedup 1.0000x reference)
#include <cuda_runtime.h>
#include <cuda_bf16.h>
#include <cstdint>

#define TPB   256
#define DCOL  544
#define MLPW  32
#define ZS    32

// ---- shared layout for LSTM (byte offsets), strides in bf16 units ----
#define ASTR   72
#define AXSTR  40
#define AB_SZ  (128 * ASTR * 2)
#define AX_SZ  (128 * AXSTR * 2)
#define OFF_AHI0 0
#define OFF_ALO0 (OFF_AHI0 + AB_SZ)
#define OFF_AHI1 (OFF_ALO0 + AB_SZ)
#define OFF_ALO1 (OFF_AHI1 + AB_SZ)
#define OFF_AX0  (OFF_ALO1 + AB_SZ)
#define OFF_AX1  (OFF_AX0 + AX_SZ)
#define SMEM_LSTM (OFF_AX1 + AX_SZ)

typedef unsigned short ush;

__device__ __forceinline__ uint32_t smem_u32(const void* p) {
    uint32_t a;
    asm("{ .reg .u64 t; cvta.to.shared.u64 t,%1; cvt.u32.u64 %0,t; }" : "=r"(a) : "l"(p));
    return a;
}
__device__ __forceinline__ void split_bf(float v, ush& hi, ush& lo) {
    __nv_bfloat16 h = __float2bfloat16(v);
    __nv_bfloat16 l = __float2bfloat16(v - __bfloat162float(h));
    hi = *(ush*)&h; lo = *(ush*)&l;
}
__device__ __forceinline__ uint32_t pk(ush a, ush b) {
    return (uint32_t)a | ((uint32_t)b << 16);
}
__device__ __forceinline__ void mma16816(float* c, const uint32_t* a, const uint32_t* b) {
    asm volatile("mma.sync.aligned.m16n8k16.row.col.f32.bf16.bf16.f32 "
        "{%0,%1,%2,%3},{%4,%5,%6,%7},{%8,%9},{%0,%1,%2,%3};"
        : "+f"(c[0]), "+f"(c[1]), "+f"(c[2]), "+f"(c[3])
        : "r"(a[0]), "r"(a[1]), "r"(a[2]), "r"(a[3]), "r"(b[0]), "r"(b[1]));
}
__device__ __forceinline__ void ldsm4(uint32_t* r, uint32_t a) {
    asm volatile("ldmatrix.sync.aligned.m8n8.x4.shared.b16 {%0,%1,%2,%3},[%4];"
        : "=r"(r[0]), "=r"(r[1]), "=r"(r[2]), "=r"(r[3]) : "r"(a));
}
__device__ __forceinline__ void ldsm4t(uint32_t* r, uint32_t a) {
    asm volatile("ldmatrix.sync.aligned.m8n8.x4.trans.shared.b16 {%0,%1,%2,%3},[%4];"
        : "=r"(r[0]), "=r"(r[1]), "=r"(r[2]), "=r"(r[3]) : "r"(a));
}
__device__ __forceinline__ float sigf(float x)  { return __fdividef(1.0f, 1.0f + __expf(-x)); }
__device__ __forceinline__ float tanhf_(float x){ return __fdividef(2.0f, 1.0f + __expf(-2.0f * x)) - 1.0f; }

// ---------------------------------------------------------------------------
// K1: bidirectional LSTM on HMMA (R6 structure). Changes vs R6:
//  - A fragments via ldmatrix.x4 (was 36 scalar LDS per mtile -> 9 ldsm)
//  - 7-MUFU fused epilogue (5 ex2 + 2 rcp per element; was 10 MUFU)
// ---------------------------------------------------------------------------
__global__ void __launch_bounds__(TPB, 1) lstm_mma_kernel(
    const float* __restrict__ last_obs, const float* __restrict__ xseq,
    const float* __restrict__ w_h0, const float* __restrict__ b_h0,
    const float* __restrict__ w_c0, const float* __restrict__ b_c0,
    const float* __restrict__ w_ih_f, const float* __restrict__ w_hh_f, const float* __restrict__ b_f,
    const float* __restrict__ w_ih_r, const float* __restrict__ w_hh_r, const float* __restrict__ b_r,
    float* __restrict__ out, int Bn, int T)
{
    extern __shared__ char sm[];
    const uint32_t sb = smem_u32(sm);
    const int tid = threadIdx.x, w = tid >> 5, lane = tid & 31;
    const int gl = lane >> 2, t2 = (lane & 3) * 2;
    const int rev = blockIdx.y, pb = blockIdx.x * 128;

    const float* w_hh = rev ? w_hh_r : w_hh_f;
    const float* w_ih = rev ? w_ih_r : w_ih_f;
    const float* bias = rev ? b_r    : b_f;

    uint32_t Bhi[4][4][2], Blo[4][4][2], Bx[4][2];
#pragma unroll
    for (int g = 0; g < 4; g++) {
        const int col = g * 64 + 8 * w + gl;
#pragma unroll
        for (int kt = 0; kt < 4; kt++) {
            const int k0 = kt * 16 + t2;
            ush h0, l0, h1, l1, h2, l2, h3, l3;
            split_bf(w_hh[(k0    ) * 256 + col], h0, l0);
            split_bf(w_hh[(k0 + 1) * 256 + col], h1, l1);
            split_bf(w_hh[(k0 + 8) * 256 + col], h2, l2);
            split_bf(w_hh[(k0 + 9) * 256 + col], h3, l3);
            Bhi[g][kt][0] = pk(h0, h1); Bhi[g][kt][1] = pk(h2, h3);
            Blo[g][kt][0] = pk(l0, l1); Blo[g][kt][1] = pk(l2, l3);
        }
        ush w0h, w0l, w1h, w1l, bh, bl;
        split_bf(w_ih[col],       w0h, w0l);
        split_bf(w_ih[256 + col], w1h, w1l);
        split_bf(bias[col],       bh,  bl);
        uint32_t pr[4] = { pk(w0h, w0h), pk(w0l, w1h), pk(w1h, w1l), pk(bh, bl) };
        Bx[g][0] = pr[lane & 3];
        Bx[g][1] = 0u;
    }

    float cst[8][4];
    {
        char* ahi0 = sm + OFF_AHI0;
        char* alo0 = sm + OFF_ALO0;
        if (!rev) {
#pragma unroll
            for (int mt = 0; mt < 8; mt++) {
#pragma unroll
                for (int rr = 0; rr < 2; rr++) {
                    const int m = mt * 16 + gl + rr * 8;
                    const float* lo = last_obs + (size_t)(pb + m) * 6;
                    float l6[6];
#pragma unroll
                    for (int k = 0; k < 6; k++) l6[k] = lo[k];
                    float hv[2];
#pragma unroll
                    for (int dd = 0; dd < 2; dd++) {
                        const int d = 8 * w + t2 + dd;
                        float hh = b_h0[d], cc = b_c0[d];
#pragma unroll
                        for (int k = 0; k < 6; k++) {
                            hh += l6[k] * w_h0[k * 64 + d];
                            cc += l6[k] * w_c0[k * 64 + d];
                        }
                        hv[dd] = hh;
                        cst[mt][rr * 2 + dd] = cc;
                    }
                    ush h0b, l0b, h1b, l1b;
                    split_bf(hv[0], h0b, l0b);
                    split_bf(hv[1], h1b, l1b);
                    const int off = m * (ASTR * 2) + (8 * w + t2) * 2;
                    *(uint32_t*)(ahi0 + off) = pk(h0b, h1b);
                    *(uint32_t*)(alo0 + off) = pk(l0b, l1b);
                }
            }
        } else {
#pragma unroll
            for (int mt = 0; mt < 8; mt++) {
#pragma unroll
                for (int rr = 0; rr < 2; rr++) {
                    const int m = mt * 16 + gl + rr * 8;
                    const int off = m * (ASTR * 2) + (8 * w + t2) * 2;
                    *(uint32_t*)(ahi0 + off) = 0u;
                    *(uint32_t*)(alo0 + off) = 0u;
                }
#pragma unroll
                for (int e = 0; e < 4; e++) cst[mt][e] = 0.f;
            }
        }
    }
    if (tid < 128) {
        const int t0 = rev ? (T - 1) : 0;
        const float2 xv = ((const float2*)xseq)[(size_t)t0 * Bn + pb + tid];
        ush x0h, x0l, x1h, x1l;
        split_bf(xv.x, x0h, x0l);
        split_bf(xv.y, x1h, x1l);
        uint4 v;
        v.x = pk(x0h, x0l); v.y = pk(x0h, x1h);
        v.z = pk(x1l, x1h); v.w = pk(0x3F80u, 0x3F80u);
        char* ax0 = sm + OFF_AX0 + tid * (AXSTR * 2);
        char* ax1 = sm + OFF_AX1 + tid * (AXSTR * 2);
        *(uint4*)ax0 = v;
        *(uint4*)(ax0 + 16) = make_uint4(0, 0, 0, 0);
        *(uint4*)(ax1 + 16) = make_uint4(0, 0, 0, 0);
    }
    __syncthreads();

    const int cb = rev * 64;
    const int dlo = 8 * w + t2;
    const int l15 = lane & 15, lhi = (lane >> 4) * 16;   // ldsm row-sel / col-byte

    for (int s = 0; s < T; s++) {
        const bool last = (s == T - 1);
        if (!last && tid < 128) {
            const int tn = rev ? (T - 2 - s) : (s + 1);
            const float2 xv = ((const float2*)xseq)[(size_t)tn * Bn + pb + tid];
            ush x0h, x0l, x1h, x1l;
            split_bf(xv.x, x0h, x0l);
            split_bf(xv.y, x1h, x1l);
            uint4 v;
            v.x = pk(x0h, x0l); v.y = pk(x0h, x1h);
            v.z = pk(x1l, x1h); v.w = pk(0x3F80u, 0x3F80u);
            *(uint4*)(sm + (((s + 1) & 1) ? OFF_AX1 : OFF_AX0) + tid * (AXSTR * 2)) = v;
        }

        const uint32_t ahiO = (s & 1) ? OFF_AHI1 : OFF_AHI0;
        const uint32_t aloO = (s & 1) ? OFF_ALO1 : OFF_ALO0;
        const uint32_t axO  = (s & 1) ? OFF_AX1  : OFF_AX0;
        char* nhi = sm + ((s & 1) ? OFF_AHI0 : OFF_AHI1);
        char* nlo = sm + ((s & 1) ? OFF_ALO0 : OFF_ALO1);

#pragma unroll 1
        for (int mt = 0; mt < 8; mt++) {
            const uint32_t arow = (uint32_t)((mt * 16 + l15) * (ASTR * 2)) + lhi;

            uint32_t ahf[4][4];
#pragma unroll
            for (int kt = 0; kt < 4; kt++)
                ldsm4(ahf[kt], sb + ahiO + arow + kt * 32);

            float C[4][4];
#pragma unroll
            for (int g = 0; g < 4; g++)
#pragma unroll
                for (int e = 0; e < 4; e++) C[g][e] = 0.f;

#pragma unroll
            for (int kt = 0; kt < 4; kt++)
#pragma unroll
                for (int g = 0; g < 4; g++)
                    mma16816(C[g], ahf[kt], Bhi[g][kt]);

#pragma unroll
            for (int kt = 0; kt < 4; kt++) {
                uint32_t alf[4];
                ldsm4(alf, sb + aloO + arow + kt * 32);
#pragma unroll
                for (int g = 0; g < 4; g++)
                    mma16816(C[g], alf, Bhi[g][kt]);
            }

#pragma unroll
            for (int kt = 0; kt < 4; kt++)
#pragma unroll
                for (int g = 0; g < 4; g++)
                    mma16816(C[g], ahf[kt], Blo[g][kt]);

            {
                uint32_t axf[4];
                ldsm4(axf, sb + axO + (uint32_t)((mt * 16 + l15) * (AXSTR * 2)) + lhi);
#pragma unroll
                for (int g = 0; g < 4; g++)
                    mma16816(C[g], axf, Bx[g]);
            }

            // fused epilogue: 5 ex2 + 2 rcp per element
            float hv[4];
#pragma unroll
            for (int e = 0; e < 4; e++) {
                const float zi = C[0][e], zf = C[1][e], zg = C[2][e], zo = C[3][e];
                const float ei = __expf(-zi);
                const float ef = __expf(-zf);
                const float eg = __expf(-2.0f * zg);
                const float pig = (1.0f + ei) * (1.0f + eg);
                const float num = cst[mt][e] * pig + (1.0f - eg) * (1.0f + ef);
                const float cn  = num * __fdividef(1.0f, (1.0f + ef) * pig);
                cst[mt][e] = cn;
                const float eo = __expf(-zo);
                const float ec = __expf(-2.0f * cn);
                hv[e] = (1.0f - ec) * __fdividef(1.0f, (1.0f + eo) * (1.0f + ec));
            }

            const int r0 = (mt * 16 + gl) * (ASTR * 2);
            const int r1 = (mt * 16 + gl + 8) * (ASTR * 2);
            if (!last) {
                ush h0b, l0b, h1b, l1b;
                split_bf(hv[0], h0b, l0b);
                split_bf(hv[1], h1b, l1b);
                *(uint32_t*)(nhi + r0 + dlo * 2) = pk(h0b, h1b);
                *(uint32_t*)(nlo + r0 + dlo * 2) = pk(l0b, l1b);
                split_bf(hv[2], h0b, l0b);
                split_bf(hv[3], h1b, l1b);
                *(uint32_t*)(nhi + r1 + dlo * 2) = pk(h0b, h1b);
                *(uint32_t*)(nlo + r1 + dlo * 2) = pk(l0b, l1b);
            } else {
                float* o0 = out + (size_t)(pb + mt * 16 + gl) * DCOL;
                float* o1 = out + (size_t)(pb + mt * 16 + gl + 8) * DCOL;
                *(float2*)&o0[cb + dlo]       = make_float2(hv[0], hv[1]);
                *(float2*)&o1[cb + dlo]       = make_float2(hv[2], hv[3]);
                *(float2*)&o0[128 + cb + dlo] = make_float2(cst[mt][0], cst[mt][1]);
                *(float2*)&o1[128 + cb + dlo] = make_float2(cst[mt][2], cst[mt][3]);
            }
        }
        __syncthreads();
    }
}

// ---------------------------------------------------------------------------
// K2: per-scene attention pooling on HMMA (R6 version, proven). UNCHANGED.
// ---------------------------------------------------------------------------
#define EPAD 264
#define GPAD 68
#define PPAD 72
#define OFF_EHI 0
#define OFF_ELO (64 * EPAD * 2)
#define OFF_PHI (OFF_ELO + 64 * EPAD * 2)
#define OFF_PLO (OFF_PHI + 64 * PPAD * 2)
#define OFF_GR  (OFF_PLO + 64 * PPAD * 2)
#define SMEM_ATTN (OFF_GR + 64 * GPAD * 4)

__global__ void __launch_bounds__(TPB) attn_mma_kernel(float* __restrict__ out,
                                                       const float* __restrict__ obs)
{
    extern __shared__ char sm[];
    const uint32_t sb = smem_u32(sm);
    const int tid = threadIdx.x, w = tid >> 5, lane = tid & 31;
    const int pbase = blockIdx.x * 64;

    for (int i = tid; i < 64 * 64; i += TPB) {
        const int p = i >> 6, c4 = i & 63;
        const float4 v = ((const float4*)(out + (size_t)(pbase + p) * DCOL))[c4];
        ush h0, l0, h1, l1, h2, l2, h3, l3;
        split_bf(v.x, h0, l0); split_bf(v.y, h1, l1);
        split_bf(v.z, h2, l2); split_bf(v.w, h3, l3);
        const int off = (p * EPAD + c4 * 4) * 2;
        *(uint2*)(sm + OFF_EHI + off) = make_uint2(pk(h0, h1), pk(h2, h3));
        *(uint2*)(sm + OFF_ELO + off) = make_uint2(pk(l0, l1), pk(l2, l3));
    }
    __syncthreads();

    {
        const int mi = w >> 1, nbase = (w & 1) * 2;
        float C[2][2][4];
#pragma unroll
        for (int a = 0; a < 2; a++)
#pragma unroll
            for (int b = 0; b < 2; b++)
#pragma unroll
                for (int e = 0; e < 4; e++) C[a][b][e] = 0.f;

        const uint32_t arow = (uint32_t)((mi * 16 + (lane & 15)) * EPAD) * 2;
        const uint32_t brow0 = (uint32_t)(((nbase    ) * 16 + (lane & 15)) * EPAD) * 2;
        const uint32_t brow1 = (uint32_t)(((nbase + 1) * 16 + (lane & 15)) * EPAD) * 2;

#pragma unroll 4
        for (int kt = 0; kt < 16; kt++) {
            const uint32_t col = (uint32_t)(kt * 16 + (lane >> 4) * 8) * 2;
            uint32_t ah[4], al[4];
            ldsm4(ah, sb + OFF_EHI + arow + col);
            ldsm4(al, sb + OFF_ELO + arow + col);
#pragma unroll
            for (int n2 = 0; n2 < 2; n2++) {
                const uint32_t brow = n2 ? brow1 : brow0;
                uint32_t bh[4], bl[4];
                ldsm4(bh, sb + OFF_EHI + brow + col);
                ldsm4(bl, sb + OFF_ELO + brow + col);
#pragma unroll
                for (int nb = 0; nb < 2; nb++) {
                    uint32_t bhp[2] = { bh[nb], bh[2 + nb] };
                    uint32_t blp[2] = { bl[nb], bl[2 + nb] };
                    mma16816(C[n2][nb], ah, bhp);
                    mma16816(C[n2][nb], al, bhp);
                    mma16816(C[n2][nb], ah, blp);
                }
            }
        }
        float* gr = (float*)(sm + OFF_GR);
        const int m0 = mi * 16 + (lane >> 2);
#pragma unroll
        for (int n2 = 0; n2 < 2; n2++)
#pragma unroll
            for (int nb = 0; nb < 2; nb++) {
                const int n0 = (nbase + n2) * 16 + nb * 8 + (lane & 3) * 2;
                *(float2*)&gr[m0 * GPAD + n0]       = make_float2(C[n2][nb][0], C[n2][nb][1]);
                *(float2*)&gr[(m0 + 8) * GPAD + n0] = make_float2(C[n2][nb][2], C[n2][nb][3]);
            }
    }
    __syncthreads();

    if (tid < 64) {
        float* gr = (float*)(sm + OFF_GR) + tid * GPAD;
        float m = -1e30f;
        for (int q = 0; q < 64; q++) m = fmaxf(m, gr[q]);
        float ssum = 0.f;
        for (int q = 0; q < 64; q++) {
            const float e = __expf(gr[q] - m);
            gr[q] = e;
            ssum += e;
        }
        const float inv = __fdividef(1.0f, ssum);
        for (int q = 0; q < 64; q++) gr[q] *= inv;
    }
    __syncthreads();

    {
        const int p = tid >> 2, q0 = (tid & 3) * 16;
        const float* gr = (const float*)(sm + OFF_GR) + p * GPAD + q0;
#pragma unroll
        for (int j = 0; j < 8; j++) {
            ush h0, l0, h1, l1;
            split_bf(gr[j * 2],     h0, l0);
            split_bf(gr[j * 2 + 1], h1, l1);
            const int off = (p * PPAD + q0 + j * 2) * 2;
            *(uint32_t*)(sm + OFF_PHI + off) = pk(h0, h1);
            *(uint32_t*)(sm + OFF_PLO + off) = pk(l0, l1);
        }
    }
    __syncthreads();

    {
        const int mi = w >> 1, dh = w & 1;
        uint32_t ph[4][4], pl[4][4];
        const uint32_t prow = (uint32_t)((mi * 16 + (lane & 15)) * PPAD) * 2;
#pragma unroll
        for (int kt = 0; kt < 4; kt++) {
            const uint32_t col = (uint32_t)(kt * 16 + (lane >> 4) * 8) * 2;
            ldsm4(ph[kt], sb + OFF_PHI + prow + col);
            ldsm4(pl[kt], sb + OFF_PLO + prow + col);
        }
        const int m0 = pbase + mi * 16 + (lane >> 2);
#pragma unroll 1
        for (int nt = 0; nt < 8; nt++) {
            const int ni = dh * 8 + nt;
            float C[2][4];
#pragma unroll
            for (int nb = 0; nb < 2; nb++)
#pragma unroll
                for (int e = 0; e < 4; e++) C[nb][e] = 0.f;
#pragma unroll
            for (int kt = 0; kt < 4; kt++) {
                const uint32_t baddr = sb + OFF_EHI +
                    (uint32_t)((kt * 16 + (lane & 15)) * EPAD + ni * 16 + (lane >> 4) * 8) * 2;
                uint32_t bh[4], bl[4];
                ldsm4t(bh, baddr);
                ldsm4t(bl, baddr + (OFF_ELO - OFF_EHI));
#pragma unroll
                for (int nb = 0; nb < 2; nb++) {
                    uint32_t bhp[2] = { bh[2 * nb], bh[2 * nb + 1] };
                    uint32_t blp[2] = { bl[2 * nb], bl[2 * nb + 1] };
                    mma16816(C[nb], ph[kt], bhp);
                    mma16816(C[nb], pl[kt], bhp);
                    mma16816(C[nb], ph[kt], blp);
                }
            }
#pragma unroll
            for (int nb = 0; nb < 2; nb++) {
                const int n0 = 256 + ni * 16 + nb * 8 + (lane & 3) * 2;
                *(float2*)&out[(size_t)m0 * DCOL + n0]       = make_float2(C[nb][0], C[nb][1]);
                *(float2*)&out[(size_t)(m0 + 8) * DCOL + n0] = make_float2(C[nb][2], C[nb][3]);
            }
        }
    }

    for (int i = tid; i < 64 * MLPW; i += TPB) {
        const int p = i >> 5, cc = i & 31;
        out[(size_t)(pbase + p) * DCOL + 512 + cc] = obs[(size_t)(pbase + p) * MLPW + cc];
    }
}

// ---------------------------------------------------------------------------
// K3: stats = dist_fc_input @ w_fc2 + b_fc2 on HMMA (R13 version, proven). UNCHANGED.
// ---------------------------------------------------------------------------
#define WSTR  560
#define FSTR  280
#define FK    272
#define OFF_WHI 0
#define OFF_WLO (OFF_WHI + 32 * WSTR * 2)
#define OFF_FHI (OFF_WLO + 32 * WSTR * 2)
#define OFF_FLO (OFF_FHI + 128 * FSTR * 2)
#define SMEM_FC2 (OFF_FLO + 128 * FSTR * 2)

__global__ void __launch_bounds__(TPB, 1) fc2_mma_kernel(
    const float* __restrict__ dfi, const float* __restrict__ wfc,
    const float* __restrict__ bz, float* __restrict__ stats)
{
    extern __shared__ char sm[];
    const uint32_t sb = smem_u32(sm);
    const int tid = threadIdx.x, wi = tid >> 5, lane = tid & 31;
    const int gl = lane >> 2, t2 = (lane & 3) * 2;
    const int rowbase = blockIdx.x * 128;

    for (int i = tid; i < DCOL * ZS; i += TPB) {
        const int n = i & 31, k = i >> 5;
        ush hi, lo;
        split_bf(wfc[k * ZS + n], hi, lo);
        *(ush*)(sm + OFF_WHI + (n * WSTR + k) * 2) = hi;
        *(ush*)(sm + OFF_WLO + (n * WSTR + k) * 2) = lo;
    }

    float C[4][4];
#pragma unroll
    for (int nt = 0; nt < 4; nt++)
#pragma unroll
        for (int e = 0; e < 4; e++) C[nt][e] = 0.f;

#pragma unroll 1
    for (int ch = 0; ch < 2; ch++) {
        __syncthreads();
        for (int i = tid; i < 128 * (FK / 4); i += TPB) {
            const int r = i / (FK / 4), c4 = i % (FK / 4);
            const float4 v = *(const float4*)(dfi + (size_t)(rowbase + r) * DCOL + ch * FK + c4 * 4);
            ush h0, l0, h1, l1, h2, l2, h3, l3;
            split_bf(v.x, h0, l0); split_bf(v.y, h1, l1);
            split_bf(v.z, h2, l2); split_bf(v.w, h3, l3);
            const int off = (r * FSTR + c4 * 4) * 2;
            *(uint2*)(sm + OFF_FHI + off) = make_uint2(pk(h0, h1), pk(h2, h3));
            *(uint2*)(sm + OFF_FLO + off) = make_uint2(pk(l0, l1), pk(l2, l3));
        }
        __syncthreads();

#pragma unroll 1
        for (int kt = 0; kt < FK / 16; kt++) {
            const uint32_t aaddr = (uint32_t)((wi * 16 + (lane & 15)) * FSTR
                                            + kt * 16 + (lane >> 4) * 8) * 2;
            uint32_t ah[4], al[4];
            ldsm4(ah, sb + OFF_FHI + aaddr);
            ldsm4(al, sb + OFF_FLO + aaddr);
            const int kk = kt * 16 + t2;
            const int kg = ch * FK + kk;
#pragma unroll
            for (int nt = 0; nt < 4; nt++) {
                const int n = nt * 8 + gl;
                uint32_t bh[2], bl[2];
                bh[0] = *(const uint32_t*)(sm + OFF_WHI + (n * WSTR + kg) * 2);
                bh[1] = *(const uint32_t*)(sm + OFF_WHI + (n * WSTR + kg + 8) * 2);
                bl[0] = *(const uint32_t*)(sm + OFF_WLO + (n * WSTR + kg) * 2);
                bl[1] = *(const uint32_t*)(sm + OFF_WLO + (n * WSTR + kg + 8) * 2);
                mma16816(C[nt], ah, bh);
                mma16816(C[nt], al, bh);
                mma16816(C[nt], ah, bl);
            }
        }
    }

    const int r0 = rowbase + wi * 16 + gl;
#pragma unroll
    for (int nt = 0; nt < 4; nt++) {
        const int n0 = nt * 8 + t2;
        const float b0 = bz[n0], b1 = bz[n0 + 1];
        *(float2*)&stats[(size_t)r0 * ZS + n0]       = make_float2(C[nt][0] + b0, C[nt][1] + b1);
        *(float2*)&stats[(size_t)(r0 + 8) * ZS + n0] = make_float2(C[nt][2] + b0, C[nt][3] + b1);
    }
}

// ---------------------------------------------------------------------------
extern "C" void kernel_launch(void* const* d_in, const int* in_sizes, int n_in,
                              void* d_out, int out_size)
{
    const float* last_obs = (const float*)d_in[0];
    const float* xseq     = (const float*)d_in[1];
    const float* obs      = (const float*)d_in[3];
    const float* w_h0     = (const float*)d_in[5];
    const float* b_h0     = (const float*)d_in[6];
    const float* w_c0     = (const float*)d_in[7];
    const float* b_c0     = (const float*)d_in[8];
    const float* w_ih_f   = (const float*)d_in[9];
    const float* w_hh_f   = (const float*)d_in[10];
    const float* b_f      = (const float*)d_in[11];
    const float* w_ih_r   = (const float*)d_in[12];
    const float* w_hh_r   = (const float*)d_in[13];
    const float* b_r      = (const float*)d_in[14];
    const float* w_fc2    = (const float*)d_in[15];
    const float* b_fc2    = (const float*)d_in[16];
    float* out = (float*)d_out;

    const int B = in_sizes[0] / 6;
    const int T = in_sizes[1] / (B * 2);
    const int S = in_sizes[2] / 2;

    cudaFuncSetAttribute(lstm_mma_kernel, cudaFuncAttributeMaxDynamicSharedMemorySize, SMEM_LSTM);
    cudaFuncSetAttribute(attn_mma_kernel, cudaFuncAttributeMaxDynamicSharedMemorySize, SMEM_ATTN);
    cudaFuncSetAttribute(fc2_mma_kernel,  cudaFuncAttributeMaxDynamicSharedMemorySize, SMEM_FC2);

    dim3 g1(B / 128, 2);
    lstm_mma_kernel<<<g1, TPB, SMEM_LSTM>>>(last_obs, xseq,
                                            w_h0, b_h0, w_c0, b_c0,
                                            w_ih_f, w_hh_f, b_f,
                                            w_ih_r, w_hh_r, b_r,
                                            out, B, T);

    attn_mma_kernel<<<S, TPB, SMEM_ATTN>>>(out, obs);

    float* stats = out + (size_t)B * DCOL;
    fc2_mma_kernel<<<B / 128, TPB, SMEM_FC2>>>(out, w_fc2, b_fc2, stats);
}

// round 17
// speedup vs baseline: 1.0508x; 1.0508x over previous
#include <cuda_runtime.h>
#include <cuda_bf16.h>
#include <cstdint>

#define TPB   256
#define DCOL  544
#define MLPW  32
#define ZS    32

// ---- LSTM shared layout (bytes) ----
#define BSTR   264                          // B tile row stride (bf16 units)
#define ASTR   72                           // h tile row stride
#define AXSB   48                           // extras row stride (bytes)
#define OFF_BHI 0
#define OFF_BLO (OFF_BHI + 64 * BSTR * 2)   // 33792
#define OFF_AHI (OFF_BLO + 64 * BSTR * 2)   // 67584
#define OFF_ALO (OFF_AHI + 128 * ASTR * 2)  // 86016
#define OFF_AX  (OFF_ALO + 128 * ASTR * 2)  // 104448
#define SMEM_LSTM (OFF_AX + 128 * AXSB)     // 110592 -> 2 blocks/SM

typedef unsigned short ush;

__device__ __forceinline__ uint32_t smem_u32(const void* p) {
    uint32_t a;
    asm("{ .reg .u64 t; cvta.to.shared.u64 t,%1; cvt.u32.u64 %0,t; }" : "=r"(a) : "l"(p));
    return a;
}
__device__ __forceinline__ void split_bf(float v, ush& hi, ush& lo) {
    __nv_bfloat16 h = __float2bfloat16(v);
    __nv_bfloat16 l = __float2bfloat16(v - __bfloat162float(h));
    hi = *(ush*)&h; lo = *(ush*)&l;
}
__device__ __forceinline__ uint32_t pk(ush a, ush b) {
    return (uint32_t)a | ((uint32_t)b << 16);
}
__device__ __forceinline__ void mma16816(float* c, const uint32_t* a, const uint32_t* b) {
    asm volatile("mma.sync.aligned.m16n8k16.row.col.f32.bf16.bf16.f32 "
        "{%0,%1,%2,%3},{%4,%5,%6,%7},{%8,%9},{%0,%1,%2,%3};"
        : "+f"(c[0]), "+f"(c[1]), "+f"(c[2]), "+f"(c[3])
        : "r"(a[0]), "r"(a[1]), "r"(a[2]), "r"(a[3]), "r"(b[0]), "r"(b[1]));
}
__device__ __forceinline__ void ldsm4(uint32_t* r, uint32_t a) {
    asm volatile("ldmatrix.sync.aligned.m8n8.x4.shared.b16 {%0,%1,%2,%3},[%4];"
        : "=r"(r[0]), "=r"(r[1]), "=r"(r[2]), "=r"(r[3]) : "r"(a));
}
__device__ __forceinline__ void ldsm4t(uint32_t* r, uint32_t a) {
    asm volatile("ldmatrix.sync.aligned.m8n8.x4.trans.shared.b16 {%0,%1,%2,%3},[%4];"
        : "=r"(r[0]), "=r"(r[1]), "=r"(r[2]), "=r"(r[3]) : "r"(a));
}
__device__ __forceinline__ float sigf(float x)  { return __fdividef(1.0f, 1.0f + __expf(-x)); }
__device__ __forceinline__ float tanhf_(float x){ return __fdividef(2.0f, 1.0f + __expf(-2.0f * x)) - 1.0f; }

// ---------------------------------------------------------------------------
// K1: bidirectional LSTM on HMMA. Weights in SMEM (not regs) -> ~120 regs ->
// 2 blocks/SM (4 warps/SMSP). Single in-place h buffer; per-mtile barrier
// separates all A-reads of a 16-row slice from its h-writes.
// ---------------------------------------------------------------------------
__global__ void __launch_bounds__(TPB, 2) lstm_mma_kernel(
    const float* __restrict__ last_obs, const float* __restrict__ xseq,
    const float* __restrict__ w_h0, const float* __restrict__ b_h0,
    const float* __restrict__ w_c0, const float* __restrict__ b_c0,
    const float* __restrict__ w_ih_f, const float* __restrict__ w_hh_f, const float* __restrict__ b_f,
    const float* __restrict__ w_ih_r, const float* __restrict__ w_hh_r, const float* __restrict__ b_r,
    float* __restrict__ out, int Bn, int T)
{
    extern __shared__ char sm[];
    const uint32_t sb = smem_u32(sm);
    const int tid = threadIdx.x, w = tid >> 5, lane = tid & 31;
    const int gl = lane >> 2, t2 = (lane & 3) * 2;
    const int rev = blockIdx.y, pb = blockIdx.x * 128;

    const float* w_hh = rev ? w_hh_r : w_hh_f;
    const float* w_ih = rev ? w_ih_r : w_ih_f;
    const float* bias = rev ? b_r    : b_f;

    // ---- B tiles: split w_hh[k][n] into smem hi/lo, stride BSTR ----
    for (int i = tid; i < 64 * 256; i += TPB) {
        const int k = i >> 8, n = i & 255;
        ush hi, lo;
        split_bf(w_hh[i], hi, lo);
        *(ush*)(sm + OFF_BHI + (k * BSTR + n) * 2) = hi;
        *(ush*)(sm + OFF_BLO + (k * BSTR + n) * 2) = lo;
    }

    // ---- Bx extras fragments (registers, 8 regs) ----
    uint32_t Bx[4][2];
#pragma unroll
    for (int g = 0; g < 4; g++) {
        const int col = g * 64 + 8 * w + gl;
        ush w0h, w0l, w1h, w1l, bh, bl;
        split_bf(w_ih[col],       w0h, w0l);
        split_bf(w_ih[256 + col], w1h, w1l);
        split_bf(bias[col],       bh,  bl);
        uint32_t pr[4] = { pk(w0h, w0h), pk(w0l, w1h), pk(w1h, w1l), pk(bh, bl) };
        Bx[g][0] = pr[lane & 3];
        Bx[g][1] = 0u;
    }

    // ---- init h0/c0 into single h buffer + cst regs ----
    float cst[8][4];
    {
        char* ahi0 = sm + OFF_AHI;
        char* alo0 = sm + OFF_ALO;
        if (!rev) {
#pragma unroll
            for (int mt = 0; mt < 8; mt++) {
#pragma unroll
                for (int rr = 0; rr < 2; rr++) {
                    const int m = mt * 16 + gl + rr * 8;
                    const float* lo = last_obs + (size_t)(pb + m) * 6;
                    float l6[6];
#pragma unroll
                    for (int k = 0; k < 6; k++) l6[k] = lo[k];
                    float hv[2];
#pragma unroll
                    for (int dd = 0; dd < 2; dd++) {
                        const int d = 8 * w + t2 + dd;
                        float hh = b_h0[d], cc = b_c0[d];
#pragma unroll
                        for (int k = 0; k < 6; k++) {
                            hh += l6[k] * w_h0[k * 64 + d];
                            cc += l6[k] * w_c0[k * 64 + d];
                        }
                        hv[dd] = hh;
                        cst[mt][rr * 2 + dd] = cc;
                    }
                    ush h0b, l0b, h1b, l1b;
                    split_bf(hv[0], h0b, l0b);
                    split_bf(hv[1], h1b, l1b);
                    const int off = m * (ASTR * 2) + (8 * w + t2) * 2;
                    *(uint32_t*)(ahi0 + off) = pk(h0b, h1b);
                    *(uint32_t*)(alo0 + off) = pk(l0b, l1b);
                }
            }
        } else {
#pragma unroll
            for (int mt = 0; mt < 8; mt++) {
#pragma unroll
                for (int rr = 0; rr < 2; rr++) {
                    const int m = mt * 16 + gl + rr * 8;
                    const int off = m * (ASTR * 2) + (8 * w + t2) * 2;
                    *(uint32_t*)(ahi0 + off) = 0u;
                    *(uint32_t*)(alo0 + off) = 0u;
                }
#pragma unroll
                for (int e = 0; e < 4; e++) cst[mt][e] = 0.f;
            }
        }
    }
    // ---- AX init for step 0 (cols 0-7 data, 8-15 zero) ----
    if (tid < 128) {
        const int t0 = rev ? (T - 1) : 0;
        const float2 xv = ((const float2*)xseq)[(size_t)t0 * Bn + pb + tid];
        ush x0h, x0l, x1h, x1l;
        split_bf(xv.x, x0h, x0l);
        split_bf(xv.y, x1h, x1l);
        uint4 v;
        v.x = pk(x0h, x0l); v.y = pk(x0h, x1h);
        v.z = pk(x1l, x1h); v.w = pk(0x3F80u, 0x3F80u);
        *(uint4*)(sm + OFF_AX + tid * AXSB)      = v;
        *(uint4*)(sm + OFF_AX + tid * AXSB + 16) = make_uint4(0, 0, 0, 0);
    }
    __syncthreads();

    const int cb = rev * 64;
    const int dlo = 8 * w + t2;
    const int l15 = lane & 15, lhi = (lane >> 4) * 16;
    // B ldsm4t base: lanes 0-15 -> BHI rows, lanes 16-31 -> BLO rows (hi+lo in one ldsm)
    const uint32_t bbase = sb + ((lane & 16) ? OFF_BLO : OFF_BHI)
                         + (uint32_t)l15 * (BSTR * 2);
    const uint32_t ncol2 = (uint32_t)(8 * w) * 2;

    for (int s = 0; s < T; s++) {
        const bool last = (s == T - 1);
        uint4 xn;
        if (!last && tid < 128) {
            const int tn = rev ? (T - 2 - s) : (s + 1);
            const float2 xv = ((const float2*)xseq)[(size_t)tn * Bn + pb + tid];
            ush x0h, x0l, x1h, x1l;
            split_bf(xv.x, x0h, x0l);
            split_bf(xv.y, x1h, x1l);
            xn.x = pk(x0h, x0l); xn.y = pk(x0h, x1h);
            xn.z = pk(x1l, x1h); xn.w = pk(0x3F80u, 0x3F80u);
        }

#pragma unroll
        for (int mt = 0; mt < 8; mt++) {
            // ---- ALL A-reads of rows [mt*16, mt*16+16) before the barrier ----
            const uint32_t arow = (uint32_t)((mt * 16 + l15) * (ASTR * 2)) + lhi;
            uint32_t ahf[4][4], alf[4][4], axf[4];
#pragma unroll
            for (int kt = 0; kt < 4; kt++) ldsm4(ahf[kt], sb + OFF_AHI + arow + kt * 32);
#pragma unroll
            for (int kt = 0; kt < 4; kt++) ldsm4(alf[kt], sb + OFF_ALO + arow + kt * 32);
            ldsm4(axf, sb + OFF_AX + (uint32_t)((mt * 16 + l15) * AXSB) + lhi);
            __syncthreads();   // all warps' reads of this slice done -> writes allowed

            float C[4][4];
#pragma unroll
            for (int g = 0; g < 4; g++)
#pragma unroll
                for (int e = 0; e < 4; e++) C[g][e] = 0.f;

#pragma unroll
            for (int kt = 0; kt < 4; kt++) {
                const uint32_t brow = (uint32_t)(kt * 16 * BSTR) * 2;
#pragma unroll
                for (int g = 0; g < 4; g++) {
                    uint32_t bb[4];   // bb[0..1] = B_hi frag, bb[2..3] = B_lo frag
                    ldsm4t(bb, bbase + brow + (uint32_t)(g * 64) * 2 + ncol2);
                    mma16816(C[g], ahf[kt], bb);
                    mma16816(C[g], alf[kt], bb);
                    mma16816(C[g], ahf[kt], bb + 2);
                }
            }
#pragma unroll
            for (int g = 0; g < 4; g++)
                mma16816(C[g], axf, Bx[g]);

            float hv[4];
#pragma unroll
            for (int e = 0; e < 4; e++) {
                const float cn = sigf(C[1][e]) * cst[mt][e] + sigf(C[0][e]) * tanhf_(C[2][e]);
                cst[mt][e] = cn;
                hv[e] = sigf(C[3][e]) * tanhf_(cn);
            }

            const int r0 = (mt * 16 + gl) * (ASTR * 2);
            const int r1 = (mt * 16 + gl + 8) * (ASTR * 2);
            if (!last) {
                ush h0b, l0b, h1b, l1b;
                split_bf(hv[0], h0b, l0b);
                split_bf(hv[1], h1b, l1b);
                *(uint32_t*)(sm + OFF_AHI + r0 + dlo * 2) = pk(h0b, h1b);
                *(uint32_t*)(sm + OFF_ALO + r0 + dlo * 2) = pk(l0b, l1b);
                split_bf(hv[2], h0b, l0b);
                split_bf(hv[3], h1b, l1b);
                *(uint32_t*)(sm + OFF_AHI + r1 + dlo * 2) = pk(h0b, h1b);
                *(uint32_t*)(sm + OFF_ALO + r1 + dlo * 2) = pk(l0b, l1b);
            } else {
                float* o0 = out + (size_t)(pb + mt * 16 + gl) * DCOL;
                float* o1 = out + (size_t)(pb + mt * 16 + gl + 8) * DCOL;
                *(float2*)&o0[cb + dlo]       = make_float2(hv[0], hv[1]);
                *(float2*)&o1[cb + dlo]       = make_float2(hv[2], hv[3]);
                *(float2*)&o0[128 + cb + dlo] = make_float2(cst[mt][0], cst[mt][1]);
                *(float2*)&o1[128 + cb + dlo] = make_float2(cst[mt][2], cst[mt][3]);
            }
        }

        // next step's x (all extras reads of this step happened before barrier mt=7)
        if (!last && tid < 128)
            *(uint4*)(sm + OFF_AX + tid * AXSB) = xn;
        __syncthreads();
    }
}

// ---------------------------------------------------------------------------
// K2: per-scene attention pooling on HMMA (R6 version, proven). UNCHANGED.
// ---------------------------------------------------------------------------
#define EPAD 264
#define GPAD 68
#define PPAD 72
#define OFF_EHI 0
#define OFF_ELO (64 * EPAD * 2)
#define OFF_PHI (OFF_ELO + 64 * EPAD * 2)
#define OFF_PLO (OFF_PHI + 64 * PPAD * 2)
#define OFF_GR  (OFF_PLO + 64 * PPAD * 2)
#define SMEM_ATTN (OFF_GR + 64 * GPAD * 4)

__global__ void __launch_bounds__(TPB) attn_mma_kernel(float* __restrict__ out,
                                                       const float* __restrict__ obs)
{
    extern __shared__ char sm[];
    const uint32_t sb = smem_u32(sm);
    const int tid = threadIdx.x, w = tid >> 5, lane = tid & 31;
    const int pbase = blockIdx.x * 64;

    for (int i = tid; i < 64 * 64; i += TPB) {
        const int p = i >> 6, c4 = i & 63;
        const float4 v = ((const float4*)(out + (size_t)(pbase + p) * DCOL))[c4];
        ush h0, l0, h1, l1, h2, l2, h3, l3;
        split_bf(v.x, h0, l0); split_bf(v.y, h1, l1);
        split_bf(v.z, h2, l2); split_bf(v.w, h3, l3);
        const int off = (p * EPAD + c4 * 4) * 2;
        *(uint2*)(sm + OFF_EHI + off) = make_uint2(pk(h0, h1), pk(h2, h3));
        *(uint2*)(sm + OFF_ELO + off) = make_uint2(pk(l0, l1), pk(l2, l3));
    }
    __syncthreads();

    {
        const int mi = w >> 1, nbase = (w & 1) * 2;
        float C[2][2][4];
#pragma unroll
        for (int a = 0; a < 2; a++)
#pragma unroll
            for (int b = 0; b < 2; b++)
#pragma unroll
                for (int e = 0; e < 4; e++) C[a][b][e] = 0.f;

        const uint32_t arow = (uint32_t)((mi * 16 + (lane & 15)) * EPAD) * 2;
        const uint32_t brow0 = (uint32_t)(((nbase    ) * 16 + (lane & 15)) * EPAD) * 2;
        const uint32_t brow1 = (uint32_t)(((nbase + 1) * 16 + (lane & 15)) * EPAD) * 2;

#pragma unroll 4
        for (int kt = 0; kt < 16; kt++) {
            const uint32_t col = (uint32_t)(kt * 16 + (lane >> 4) * 8) * 2;
            uint32_t ah[4], al[4];
            ldsm4(ah, sb + OFF_EHI + arow + col);
            ldsm4(al, sb + OFF_ELO + arow + col);
#pragma unroll
            for (int n2 = 0; n2 < 2; n2++) {
                const uint32_t brow = n2 ? brow1 : brow0;
                uint32_t bh[4], bl[4];
                ldsm4(bh, sb + OFF_EHI + brow + col);
                ldsm4(bl, sb + OFF_ELO + brow + col);
#pragma unroll
                for (int nb = 0; nb < 2; nb++) {
                    uint32_t bhp[2] = { bh[nb], bh[2 + nb] };
                    uint32_t blp[2] = { bl[nb], bl[2 + nb] };
                    mma16816(C[n2][nb], ah, bhp);
                    mma16816(C[n2][nb], al, bhp);
                    mma16816(C[n2][nb], ah, blp);
                }
            }
        }
        float* gr = (float*)(sm + OFF_GR);
        const int m0 = mi * 16 + (lane >> 2);
#pragma unroll
        for (int n2 = 0; n2 < 2; n2++)
#pragma unroll
            for (int nb = 0; nb < 2; nb++) {
                const int n0 = (nbase + n2) * 16 + nb * 8 + (lane & 3) * 2;
                *(float2*)&gr[m0 * GPAD + n0]       = make_float2(C[n2][nb][0], C[n2][nb][1]);
                *(float2*)&gr[(m0 + 8) * GPAD + n0] = make_float2(C[n2][nb][2], C[n2][nb][3]);
            }
    }
    __syncthreads();

    if (tid < 64) {
        float* gr = (float*)(sm + OFF_GR) + tid * GPAD;
        float m = -1e30f;
        for (int q = 0; q < 64; q++) m = fmaxf(m, gr[q]);
        float ssum = 0.f;
        for (int q = 0; q < 64; q++) {
            const float e = __expf(gr[q] - m);
            gr[q] = e;
            ssum += e;
        }
        const float inv = __fdividef(1.0f, ssum);
        for (int q = 0; q < 64; q++) gr[q] *= inv;
    }
    __syncthreads();

    {
        const int p = tid >> 2, q0 = (tid & 3) * 16;
        const float* gr = (const float*)(sm + OFF_GR) + p * GPAD + q0;
#pragma unroll
        for (int j = 0; j < 8; j++) {
            ush h0, l0, h1, l1;
            split_bf(gr[j * 2],     h0, l0);
            split_bf(gr[j * 2 + 1], h1, l1);
            const int off = (p * PPAD + q0 + j * 2) * 2;
            *(uint32_t*)(sm + OFF_PHI + off) = pk(h0, h1);
            *(uint32_t*)(sm + OFF_PLO + off) = pk(l0, l1);
        }
    }
    __syncthreads();

    {
        const int mi = w >> 1, dh = w & 1;
        uint32_t ph[4][4], pl[4][4];
        const uint32_t prow = (uint32_t)((mi * 16 + (lane & 15)) * PPAD) * 2;
#pragma unroll
        for (int kt = 0; kt < 4; kt++) {
            const uint32_t col = (uint32_t)(kt * 16 + (lane >> 4) * 8) * 2;
            ldsm4(ph[kt], sb + OFF_PHI + prow + col);
            ldsm4(pl[kt], sb + OFF_PLO + prow + col);
        }
        const int m0 = pbase + mi * 16 + (lane >> 2);
#pragma unroll 1
        for (int nt = 0; nt < 8; nt++) {
            const int ni = dh * 8 + nt;
            float C[2][4];
#pragma unroll
            for (int nb = 0; nb < 2; nb++)
#pragma unroll
                for (int e = 0; e < 4; e++) C[nb][e] = 0.f;
#pragma unroll
            for (int kt = 0; kt < 4; kt++) {
                const uint32_t baddr = sb + OFF_EHI +
                    (uint32_t)((kt * 16 + (lane & 15)) * EPAD + ni * 16 + (lane >> 4) * 8) * 2;
                uint32_t bh[4], bl[4];
                ldsm4t(bh, baddr);
                ldsm4t(bl, baddr + (OFF_ELO - OFF_EHI));
#pragma unroll
                for (int nb = 0; nb < 2; nb++) {
                    uint32_t bhp[2] = { bh[2 * nb], bh[2 * nb + 1] };
                    uint32_t blp[2] = { bl[2 * nb], bl[2 * nb + 1] };
                    mma16816(C[nb], ph[kt], bhp);
                    mma16816(C[nb], pl[kt], bhp);
                    mma16816(C[nb], ph[kt], blp);
                }
            }
#pragma unroll
            for (int nb = 0; nb < 2; nb++) {
                const int n0 = 256 + ni * 16 + nb * 8 + (lane & 3) * 2;
                *(float2*)&out[(size_t)m0 * DCOL + n0]       = make_float2(C[nb][0], C[nb][1]);
                *(float2*)&out[(size_t)(m0 + 8) * DCOL + n0] = make_float2(C[nb][2], C[nb][3]);
            }
        }
    }

    for (int i = tid; i < 64 * MLPW; i += TPB) {
        const int p = i >> 5, cc = i & 31;
        out[(size_t)(pbase + p) * DCOL + 512 + cc] = obs[(size_t)(pbase + p) * MLPW + cc];
    }
}

// ---------------------------------------------------------------------------
// K3: stats = dist_fc_input @ w_fc2 + b_fc2 on HMMA (R13 version, proven). UNCHANGED.
// ---------------------------------------------------------------------------
#define WSTR  560
#define FSTR  280
#define FK    272
#define OFF_WHI 0
#define OFF_WLO (OFF_WHI + 32 * WSTR * 2)
#define OFF_FHI (OFF_WLO + 32 * WSTR * 2)
#define OFF_FLO (OFF_FHI + 128 * FSTR * 2)
#define SMEM_FC2 (OFF_FLO + 128 * FSTR * 2)

__global__ void __launch_bounds__(TPB, 1) fc2_mma_kernel(
    const float* __restrict__ dfi, const float* __restrict__ wfc,
    const float* __restrict__ bz, float* __restrict__ stats)
{
    extern __shared__ char sm[];
    const uint32_t sb = smem_u32(sm);
    const int tid = threadIdx.x, wi = tid >> 5, lane = tid & 31;
    const int gl = lane >> 2, t2 = (lane & 3) * 2;
    const int rowbase = blockIdx.x * 128;

    for (int i = tid; i < DCOL * ZS; i += TPB) {
        const int n = i & 31, k = i >> 5;
        ush hi, lo;
        split_bf(wfc[k * ZS + n], hi, lo);
        *(ush*)(sm + OFF_WHI + (n * WSTR + k) * 2) = hi;
        *(ush*)(sm + OFF_WLO + (n * WSTR + k) * 2) = lo;
    }

    float C[4][4];
#pragma unroll
    for (int nt = 0; nt < 4; nt++)
#pragma unroll
        for (int e = 0; e < 4; e++) C[nt][e] = 0.f;

#pragma unroll 1
    for (int ch = 0; ch < 2; ch++) {
        __syncthreads();
        for (int i = tid; i < 128 * (FK / 4); i += TPB) {
            const int r = i / (FK / 4), c4 = i % (FK / 4);
            const float4 v = *(const float4*)(dfi + (size_t)(rowbase + r) * DCOL + ch * FK + c4 * 4);
            ush h0, l0, h1, l1, h2, l2, h3, l3;
            split_bf(v.x, h0, l0); split_bf(v.y, h1, l1);
            split_bf(v.z, h2, l2); split_bf(v.w, h3, l3);
            const int off = (r * FSTR + c4 * 4) * 2;
            *(uint2*)(sm + OFF_FHI + off) = make_uint2(pk(h0, h1), pk(h2, h3));
            *(uint2*)(sm + OFF_FLO + off) = make_uint2(pk(l0, l1), pk(l2, l3));
        }
        __syncthreads();

#pragma unroll 1
        for (int kt = 0; kt < FK / 16; kt++) {
            const uint32_t aaddr = (uint32_t)((wi * 16 + (lane & 15)) * FSTR
                                            + kt * 16 + (lane >> 4) * 8) * 2;
            uint32_t ah[4], al[4];
            ldsm4(ah, sb + OFF_FHI + aaddr);
            ldsm4(al, sb + OFF_FLO + aaddr);
            const int kk = kt * 16 + t2;
            const int kg = ch * FK + kk;
#pragma unroll
            for (int nt = 0; nt < 4; nt++) {
                const int n = nt * 8 + gl;
                uint32_t bh[2], bl[2];
                bh[0] = *(const uint32_t*)(sm + OFF_WHI + (n * WSTR + kg) * 2);
                bh[1] = *(const uint32_t*)(sm + OFF_WHI + (n * WSTR + kg + 8) * 2);
                bl[0] = *(const uint32_t*)(sm + OFF_WLO + (n * WSTR + kg) * 2);
                bl[1] = *(const uint32_t*)(sm + OFF_WLO + (n * WSTR + kg + 8) * 2);
                mma16816(C[nt], ah, bh);
                mma16816(C[nt], al, bh);
                mma16816(C[nt], ah, bl);
            }
        }
    }

    const int r0 = rowbase + wi * 16 + gl;
#pragma unroll
    for (int nt = 0; nt < 4; nt++) {
        const int n0 = nt * 8 + t2;
        const float b0 = bz[n0], b1 = bz[n0 + 1];
        *(float2*)&stats[(size_t)r0 * ZS + n0]       = make_float2(C[nt][0] + b0, C[nt][1] + b1);
        *(float2*)&stats[(size_t)(r0 + 8) * ZS + n0] = make_float2(C[nt][2] + b0, C[nt][3] + b1);
    }
}

// ---------------------------------------------------------------------------
extern "C" void kernel_launch(void* const* d_in, const int* in_sizes, int n_in,
                              void* d_out, int out_size)
{
    const float* last_obs = (const float*)d_in[0];
    const float* xseq     = (const float*)d_in[1];
    const float* obs      = (const float*)d_in[3];
    const float* w_h0     = (const float*)d_in[5];
    const float* b_h0     = (const float*)d_in[6];
    const float* w_c0     = (const float*)d_in[7];
    const float* b_c0     = (const float*)d_in[8];
    const float* w_ih_f   = (const float*)d_in[9];
    const float* w_hh_f   = (const float*)d_in[10];
    const float* b_f      = (const float*)d_in[11];
    const float* w_ih_r   = (const float*)d_in[12];
    const float* w_hh_r   = (const float*)d_in[13];
    const float* b_r      = (const float*)d_in[14];
    const float* w_fc2    = (const float*)d_in[15];
    const float* b_fc2    = (const float*)d_in[16];
    float* out = (float*)d_out;

    const int B = in_sizes[0] / 6;
    const int T = in_sizes[1] / (B * 2);
    const int S = in_sizes[2] / 2;

    cudaFuncSetAttribute(lstm_mma_kernel, cudaFuncAttributeMaxDynamicSharedMemorySize, SMEM_LSTM);
    cudaFuncSetAttribute(attn_mma_kernel, cudaFuncAttributeMaxDynamicSharedMemorySize, SMEM_ATTN);
    cudaFuncSetAttribute(fc2_mma_kernel,  cudaFuncAttributeMaxDynamicSharedMemorySize, SMEM_FC2);

    dim3 g1(B / 128, 2);
    lstm_mma_kernel<<<g1, TPB, SMEM_LSTM>>>(last_obs, xseq,
                                            w_h0, b_h0, w_c0, b_c0,
                                            w_ih_f, w_hh_f, b_f,
                                            w_ih_r, w_hh_r, b_r,
                                            out, B, T);

    attn_mma_kernel<<<S, TPB, SMEM_ATTN>>>(out, obs);

    float* stats = out + (size_t)B * DCOL;
    fc2_mma_kernel<<<B / 128, TPB, SMEM_FC2>>>(out, w_fc2, b_fc2, stats);
}